// round 1
// baseline (speedup 1.0000x reference)
#include <cuda_runtime.h>
#include <cub/block/block_radix_sort.cuh>

// Problem constants (match reference: x = [4096, 8192, 1] f32, G = 7)
constexpr int B_ROWS = 4096;
constexpr int I_COLS = 8192;
constexpr int G = 7;

constexpr int BT  = 1024;  // threads per block
constexpr int IPT = 8;     // items per thread (BT*IPT == I_COLS)

__global__ void __launch_bounds__(BT)
portfolio_sort_kernel(const float* __restrict__ x, float* __restrict__ out)
{
    using Sorter = cub::BlockRadixSort<float, BT, IPT, int>;
    __shared__ typename Sorter::TempStorage temp;
    __shared__ float s_top[G];   // sorted_x[0:G]       (descending)
    __shared__ float s_bot[G];   // sorted_x[I-G:I]
    __shared__ float s_win[G];   // softmax(top)
    __shared__ float s_los[G];   // -softmax(1 - bot)

    const int row = blockIdx.x;
    const float* xr = x + (size_t)row * I_COLS;

    // Blocked load: thread t owns elements [t*IPT, t*IPT+IPT) -> 2x float4,
    // fully coalesced (each warp reads 1KB contiguous). Blocked order ==
    // original order, so cub's stable radix sort reproduces jnp.argsort
    // tie-breaking exactly.
    float keys[IPT];
    int   vals[IPT];
    const int base = threadIdx.x * IPT;
    const float4* xr4 = reinterpret_cast<const float4*>(xr + base);
    float4 a = xr4[0];
    float4 b = xr4[1];
    keys[0] = a.x; keys[1] = a.y; keys[2] = a.z; keys[3] = a.w;
    keys[4] = b.x; keys[5] = b.y; keys[6] = b.z; keys[7] = b.w;
    #pragma unroll
    for (int i = 0; i < IPT; i++) vals[i] = base + i;

    Sorter(temp).SortDescendingBlockedToStriped(keys, vals);

    // Striped arrangement: item i of thread t holds rank (i*BT + t).
    #pragma unroll
    for (int i = 0; i < IPT; i++) {
        int r = i * BT + threadIdx.x;
        if (r < G)           s_top[r] = keys[i];
        if (r >= I_COLS - G) s_bot[r - (I_COLS - G)] = keys[i];
    }
    __syncthreads();

    if (threadIdx.x == 0) {
        // winner = softmax(sorted_x[:G])
        float m = s_top[0];
        #pragma unroll
        for (int i = 1; i < G; i++) m = fmaxf(m, s_top[i]);
        float e[G], s = 0.0f;
        #pragma unroll
        for (int i = 0; i < G; i++) { e[i] = expf(s_top[i] - m); s += e[i]; }
        float inv = 1.0f / s;
        #pragma unroll
        for (int i = 0; i < G; i++) s_win[i] = e[i] * inv;

        // loser = -softmax(1 - sorted_x[-G:])
        float t0 = 1.0f - s_bot[0];
        float m2 = t0;
        #pragma unroll
        for (int i = 1; i < G; i++) m2 = fmaxf(m2, 1.0f - s_bot[i]);
        float e2[G], s2 = 0.0f;
        #pragma unroll
        for (int i = 0; i < G; i++) { e2[i] = expf((1.0f - s_bot[i]) - m2); s2 += e2[i]; }
        float inv2 = 1.0f / s2;
        #pragma unroll
        for (int i = 0; i < G; i++) s_los[i] = -e2[i] * inv2;
    }
    __syncthreads();

    // Output layout: [b_c (B*I f32)] then [sorted_indices (B*I, written as f32)]
    float* bc = out + (size_t)row * I_COLS;
    float* si = out + (size_t)B_ROWS * I_COLS + (size_t)row * I_COLS;
    #pragma unroll
    for (int i = 0; i < IPT; i++) {
        int r = i * BT + threadIdx.x;
        float v = 0.0f;
        if (r < G)                v = s_win[r];
        else if (r >= I_COLS - G) v = s_los[r - (I_COLS - G)];
        bc[r] = v;
        si[r] = (float)vals[i];
    }
}

extern "C" void kernel_launch(void* const* d_in, const int* in_sizes, int n_in,
                              void* d_out, int out_size)
{
    (void)in_sizes; (void)n_in; (void)out_size;
    const float* x = (const float*)d_in[0];
    float* out = (float*)d_out;
    portfolio_sort_kernel<<<B_ROWS, BT>>>(x, out);
}